// round 13
// baseline (speedup 1.0000x reference)
#include <cuda_runtime.h>
#include <cuda_bf16.h>
#include <cstdint>

#define B_    512
#define T_    128
#define ID_   128
#define HD_   256
#define G4_   1024
#define OUTD_ 128
#define BT_   65536

typedef unsigned long long ull;

// ---------------- scratch ----------------
__device__ unsigned g_Wfrag[2][8][16][16][2][32][2];  // [dir][q][kt][nt][plane][lane][pair]
__device__ float g_Wip[2][ID_][G4_];                  // Wi, permuted cols colp = dim*4+g
__device__ float g_bpp[2][G4_];
__device__ float g_gx[2][(size_t)BT_ * G4_];
__device__ unsigned g_hexu[2][2][8][64][256];         // [par][dir][rb][row][dim] (hi|lo<<16)
__device__ float g_x1[(size_t)B_ * T_ * 2 * HD_];
__device__ float g_x2[(size_t)B_ * T_ * HD_];
__device__ float g_x3[(size_t)B_ * T_ * HD_];
__device__ float g_x4[(size_t)B_ * T_ * OUTD_];

// ---------------- helpers ----------------
__device__ __forceinline__ ull fma2(ull a, ull b, ull c) {
    ull d; asm("fma.rn.f32x2 %0, %1, %2, %3;" : "=l"(d) : "l"(a), "l"(b), "l"(c)); return d;
}
__device__ __forceinline__ ull dupf(float v) {
    ull r; unsigned u = __float_as_uint(v);
    asm("mov.b64 %0, {%1, %1};" : "=l"(r) : "r"(u)); return r;
}
__device__ __forceinline__ float lo32(ull v) { return __uint_as_float((unsigned)v); }
__device__ __forceinline__ float hi32(ull v) { return __uint_as_float((unsigned)(v >> 32)); }
__device__ __forceinline__ float sigm(float x) { return 1.f / (1.f + __expf(-x)); }
__device__ __forceinline__ float tanhp(float x) { return fmaf(2.f, sigm(2.f * x), -1.f); }
__device__ __forceinline__ uint32_t smem_u32(const void* p) {
    uint32_t a;
    asm("{ .reg .u64 t; cvta.to.shared.u64 t, %1; cvt.u32.u64 %0, t; }" : "=r"(a) : "l"(p));
    return a;
}
#define CLUSTER_SYNC() do { \
    asm volatile("barrier.cluster.arrive.aligned;" ::: "memory"); \
    asm volatile("barrier.cluster.wait.aligned;" ::: "memory"); } while (0)

#define MMA_BF16(d, a, b) \
    asm volatile("mma.sync.aligned.m16n8k16.row.col.f32.bf16.bf16.f32 " \
        "{%0,%1,%2,%3}, {%4,%5,%6,%7}, {%8,%9}, {%0,%1,%2,%3};" \
        : "+f"((d)[0]), "+f"((d)[1]), "+f"((d)[2]), "+f"((d)[3]) \
        : "r"((a)[0]), "r"((a)[1]), "r"((a)[2]), "r"((a)[3]), "r"((b)[0]), "r"((b)[1]))

// ---------------- prep: pack B fragments (split-bf16), permuted Wi + bias, zero h ----------------
__global__ void prep_kernel(const float* __restrict__ Wh_f, const float* __restrict__ Wh_r,
                            const float* __restrict__ Wi_f, const float* __restrict__ Wi_r,
                            const float* __restrict__ bi_f, const float* __restrict__ bh_f,
                            const float* __restrict__ bi_r, const float* __restrict__ bh_r) {
    int idx = blockIdx.x * blockDim.x + threadIdx.x;
    int stride = gridDim.x * blockDim.x;
    // B fragments: m16n8k16 col-major B; lane holds (k = m*2+{0,1}(+8*pair), n = gid)
    const int wft = 2 * 8 * 16 * 16 * 2 * 32 * 2;
    unsigned* wf = &g_Wfrag[0][0][0][0][0][0][0];
    for (int i = idx; i < wft; i += stride) {
        int tmp = i;
        int pr = tmp & 1; tmp >>= 1;
        int lane = tmp & 31; tmp >>= 5;
        int plane = tmp & 1; tmp >>= 1;
        int nt = tmp & 15; tmp >>= 4;
        int kt = tmp & 15; tmp >>= 4;
        int q = tmp & 7, dir = tmp >> 3;
        int n = nt * 8 + (lane >> 2);
        int k0 = kt * 16 + (lane & 3) * 2 + pr * 8;
        int sc = (n & 3) * 256 + q * 32 + (n >> 2);   // n = dim*4+g
        const float* Wh = dir ? Wh_r : Wh_f;
        float w0 = Wh[k0 * G4_ + sc], w1 = Wh[(k0 + 1) * G4_ + sc];
        unsigned e0, e1;
        __nv_bfloat16 h0 = __float2bfloat16(w0), h1 = __float2bfloat16(w1);
        if (plane == 0) {
            e0 = __bfloat16_as_ushort(h0); e1 = __bfloat16_as_ushort(h1);
        } else {
            e0 = __bfloat16_as_ushort(__float2bfloat16(w0 - __bfloat162float(h0)));
            e1 = __bfloat16_as_ushort(__float2bfloat16(w1 - __bfloat162float(h1)));
        }
        wf[i] = e0 | (e1 << 16);
    }
    const int witotal = 2 * ID_ * G4_;
    for (int i = idx; i < witotal; i += stride) {
        int dir = i / (ID_ * G4_), r = i % (ID_ * G4_);
        int k = r >> 10, colp = r & 1023;
        int dim = colp >> 2, g = colp & 3;
        const float* Wi = dir ? Wi_r : Wi_f;
        g_Wip[dir][k][colp] = Wi[k * G4_ + g * 256 + dim];
    }
    for (int i = idx; i < 2 * G4_; i += stride) {
        int dir = i >> 10, colp = i & 1023;
        int sc = (colp & 3) * 256 + (colp >> 2);
        g_bpp[dir][colp] = dir ? (bi_r[sc] + bh_r[sc]) : (bi_f[sc] + bh_f[sc]);
    }
    unsigned* hz = &g_hexu[0][0][0][0][0];
    for (int i = idx; i < 2 * 8 * 64 * 256; i += stride) hz[i] = 0u;
}

// ---------------- mma.sync recurrent LSTM ----------------
// 128 CTAs x 256 thr = 16 clusters of 8. cid = bid>>3: dir = cid>>3, rb = cid&7 (64 rows).
// Rank q: N=128 gate cols (dims q*32..+32, n = dl*4+g). Warp (mw = w>>1, nh = w&1) = m16 x n64.
// Weights: fragment-packed, SMEM-resident. h: split-bf16 via L2 exchange + cluster barrier.
#define APITCH  528
#define AHI_OFF 131072
#define ALO_OFF (131072 + 64 * APITCH)
#define LSTM_SMEM (ALO_OFF + 64 * APITCH)

__global__ __launch_bounds__(256, 1) __cluster_dims__(8, 1, 1)
void lstm_kernel() {
    extern __shared__ char sm[];
    const uint32_t sb = smem_u32(sm);
    const int tid = threadIdx.x, lane = tid & 31, w = tid >> 5;
    const int cid = blockIdx.x >> 3, dir = cid >> 3, rb = cid & 7, b0 = rb * 64;
    unsigned rank; asm("mov.u32 %0, %%cluster_ctarank;" : "=r"(rank));
    const int q = (int)rank;
    const int mw = w >> 1, nh = w & 1;

    {   // resident weight fragments (128KB)
        const uint4* src = (const uint4*)&g_Wfrag[dir][q][0][0][0][0][0];
        uint4* dst = (uint4*)sm;
        for (int i = tid; i < 8192; i += 256) dst[i] = src[i];
    }
    const int gid = lane >> 2, m = lane & 3;
    const int row_eff = mw * 16 + gid + ((lane & 1) ? 8 : 0);   // local row owned post-shuffle
    const int dlbit = (lane >> 1) & 1;
    const uint32_t aoff = (uint32_t)((mw * 16 + gid) * APITCH + m * 4);

    float cst[8];
#pragma unroll
    for (int j = 0; j < 8; j++) cst[j] = 0.f;
    __syncthreads();

#pragma unroll 1
    for (int t = 0; t < T_; t++) {
        const int par = t & 1, ts = dir ? (T_ - 1 - t) : t;

        // stage h(t) planes: global (hi|lo u32) -> smem bf16 planes [row][k], pitch 528B
#pragma unroll
        for (int it = 0; it < 16; it++) {
            int idx = tid + 256 * it;
            int r = idx >> 6, db = (idx & 63) * 4;
            const unsigned* gp = &g_hexu[par][dir][rb][r][db];
            unsigned v0, v1, v2, v3;
            asm volatile("ld.global.cg.v4.u32 {%0,%1,%2,%3}, [%4];"
                         : "=r"(v0), "=r"(v1), "=r"(v2), "=r"(v3) : "l"(gp));
            unsigned hi0 = __byte_perm(v0, v1, 0x5410), hi1 = __byte_perm(v2, v3, 0x5410);
            unsigned lo0 = __byte_perm(v0, v1, 0x7632), lo1 = __byte_perm(v2, v3, 0x7632);
            uint32_t so = (uint32_t)(r * APITCH + db * 2);
            asm volatile("st.shared.v2.u32 [%0], {%1,%2};" :: "r"(sb + AHI_OFF + so), "r"(hi0), "r"(hi1));
            asm volatile("st.shared.v2.u32 [%0], {%1,%2};" :: "r"(sb + ALO_OFF + so), "r"(lo0), "r"(lo1));
        }
        __syncthreads();

        // gx for this thread's 8 cells
        float4 gxv[8];
        {
            const float* gb = &g_gx[dir][0]
                + ((size_t)(b0 + row_eff) * T_ + ts) * G4_ + (q * 32 + nh * 16 + dlbit) * 4;
#pragma unroll
            for (int nt = 0; nt < 8; nt++) gxv[nt] = *(const float4*)(gb + nt * 8);
        }

        // mma: D[8 n-tiles][4], 3 split terms, K=256
        float d[8][4];
#pragma unroll
        for (int nt = 0; nt < 8; nt++)
#pragma unroll
            for (int j = 0; j < 4; j++) d[nt][j] = 0.f;

#pragma unroll 1
        for (int kt = 0; kt < 16; kt++) {
            unsigned ah[4], al[4];
            uint32_t ab = sb + aoff + (uint32_t)(kt * 32);
            asm volatile("ld.shared.b32 %0, [%1];" : "=r"(ah[0]) : "r"(ab + AHI_OFF));
            asm volatile("ld.shared.b32 %0, [%1];" : "=r"(ah[1]) : "r"(ab + AHI_OFF + 8 * APITCH));
            asm volatile("ld.shared.b32 %0, [%1];" : "=r"(ah[2]) : "r"(ab + AHI_OFF + 16));
            asm volatile("ld.shared.b32 %0, [%1];" : "=r"(ah[3]) : "r"(ab + AHI_OFF + 8 * APITCH + 16));
            asm volatile("ld.shared.b32 %0, [%1];" : "=r"(al[0]) : "r"(ab + ALO_OFF));
            asm volatile("ld.shared.b32 %0, [%1];" : "=r"(al[1]) : "r"(ab + ALO_OFF + 8 * APITCH));
            asm volatile("ld.shared.b32 %0, [%1];" : "=r"(al[2]) : "r"(ab + ALO_OFF + 16));
            asm volatile("ld.shared.b32 %0, [%1];" : "=r"(al[3]) : "r"(ab + ALO_OFF + 8 * APITCH + 16));
            uint32_t bbase = sb + (uint32_t)(((kt * 16 + nh * 8) * 2) * 256 + lane * 8);
#pragma unroll
            for (int nt = 0; nt < 8; nt++) {
                unsigned bh[2], bl[2];
                uint32_t ba = bbase + (uint32_t)(nt * 512);
                asm volatile("ld.shared.v2.u32 {%0,%1}, [%2];" : "=r"(bh[0]), "=r"(bh[1]) : "r"(ba));
                asm volatile("ld.shared.v2.u32 {%0,%1}, [%2];" : "=r"(bl[0]), "=r"(bl[1]) : "r"(ba + 256));
                MMA_BF16(d[nt], ah, bh);
                MMA_BF16(d[nt], al, bh);
                MMA_BF16(d[nt], ah, bl);
            }
        }

        // update: shuffle-pair (f,i)<->(a,o), one (row,dim) cell per lane per n-tile
#pragma unroll
        for (int nt = 0; nt < 8; nt++) {
            float s0 = __shfl_xor_sync(0xffffffffu, d[nt][0], 1);
            float s1 = __shfl_xor_sync(0xffffffffu, d[nt][1], 1);
            float s2 = __shfl_xor_sync(0xffffffffu, d[nt][2], 1);
            float s3 = __shfl_xor_sync(0xffffffffu, d[nt][3], 1);
            float gf, gi, ga, go;
            if (lane & 1) { gf = s2; gi = s3; ga = d[nt][2]; go = d[nt][3]; }
            else          { gf = d[nt][0]; gi = d[nt][1]; ga = s0; go = s1; }
            gf += gxv[nt].x; gi += gxv[nt].y; ga += gxv[nt].z; go += gxv[nt].w;
            float f = sigm(gf), ii = sigm(gi), a = tanhp(ga), o = sigm(go);
            float cc = fmaf(f, cst[nt], ii * a);
            cst[nt] = cc;
            float hv = o * tanhp(cc);
            int dl = nh * 16 + 2 * nt + dlbit;
            g_x1[((size_t)(b0 + row_eff) * T_ + t) * 512 + dir * 256 + q * 32 + dl] = hv;
            __nv_bfloat16 hb = __float2bfloat16(hv);
            __nv_bfloat16 lb = __float2bfloat16(hv - __bfloat162float(hb));
            g_hexu[par ^ 1][dir][rb][row_eff][q * 32 + dl] =
                (unsigned)__bfloat16_as_ushort(hb) | ((unsigned)__bfloat16_as_ushort(lb) << 16);
        }
        __threadfence();
        CLUSTER_SYNC();
    }
}

// ---------------- fp32x2 GEMM with bias + optional leaky-relu ----------------
template <int ACT>
__global__ __launch_bounds__(256) void gemm_kernel(const float* __restrict__ A,
                                                   const float* __restrict__ W,
                                                   const float* __restrict__ bias,
                                                   float* __restrict__ C,
                                                   int M, int N, int K) {
    __shared__ __align__(16) float smA[16][64];
    __shared__ __align__(16) float smW[16][128];
    const int tid = threadIdx.x;
    const int n0 = blockIdx.x * 128, m0 = blockIdx.y * 64;
    const int col = (tid & 31) * 4, rg = (tid >> 5) * 8;
    ull acc[4][4];
#pragma unroll
    for (int rp = 0; rp < 4; rp++)
#pragma unroll
        for (int c = 0; c < 4; c++) acc[rp][c] = 0ull;
    const int la_r = tid >> 2, la_k = (tid & 3) * 4;
    const int lw_n = (tid & 31) * 4, lw_k = tid >> 5;
    for (int k0 = 0; k0 < K; k0 += 16) {
        float4 av = *(const float4*)&A[(size_t)(m0 + la_r) * K + k0 + la_k];
        smA[la_k + 0][la_r] = av.x; smA[la_k + 1][la_r] = av.y;
        smA[la_k + 2][la_r] = av.z; smA[la_k + 3][la_r] = av.w;
        *(float4*)&smW[lw_k][lw_n]     = *(const float4*)&W[(size_t)(k0 + lw_k) * N + n0 + lw_n];
        *(float4*)&smW[lw_k + 8][lw_n] = *(const float4*)&W[(size_t)(k0 + lw_k + 8) * N + n0 + lw_n];
        __syncthreads();
#pragma unroll
        for (int kk = 0; kk < 16; kk++) {
            float4 wv = *(const float4*)&smW[kk][col];
            ull wd0 = dupf(wv.x), wd1 = dupf(wv.y), wd2 = dupf(wv.z), wd3 = dupf(wv.w);
#pragma unroll
            for (int rp = 0; rp < 4; rp++) {
                ull hp = *(const ull*)&smA[kk][rg + 2 * rp];
                acc[rp][0] = fma2(hp, wd0, acc[rp][0]);
                acc[rp][1] = fma2(hp, wd1, acc[rp][1]);
                acc[rp][2] = fma2(hp, wd2, acc[rp][2]);
                acc[rp][3] = fma2(hp, wd3, acc[rp][3]);
            }
        }
        __syncthreads();
    }
    const float4 bv = *(const float4*)&bias[n0 + col];
#pragma unroll
    for (int rp = 0; rp < 4; rp++) {
        const int row0 = m0 + rg + 2 * rp;
        float4 v0, v1;
        v0.x = lo32(acc[rp][0]) + bv.x; v0.y = lo32(acc[rp][1]) + bv.y;
        v0.z = lo32(acc[rp][2]) + bv.z; v0.w = lo32(acc[rp][3]) + bv.w;
        v1.x = hi32(acc[rp][0]) + bv.x; v1.y = hi32(acc[rp][1]) + bv.y;
        v1.z = hi32(acc[rp][2]) + bv.z; v1.w = hi32(acc[rp][3]) + bv.w;
        if (ACT) {
            v0.x = fmaxf(v0.x, 0.1f * v0.x); v0.y = fmaxf(v0.y, 0.1f * v0.y);
            v0.z = fmaxf(v0.z, 0.1f * v0.z); v0.w = fmaxf(v0.w, 0.1f * v0.w);
            v1.x = fmaxf(v1.x, 0.1f * v1.x); v1.y = fmaxf(v1.y, 0.1f * v1.y);
            v1.z = fmaxf(v1.z, 0.1f * v1.z); v1.w = fmaxf(v1.w, 0.1f * v1.w);
        }
        *(float4*)&C[(size_t)row0 * N + n0 + col]       = v0;
        *(float4*)&C[(size_t)(row0 + 1) * N + n0 + col] = v1;
    }
}

// ---------------- head ----------------
__global__ __launch_bounds__(256) void head_kernel(float* __restrict__ out) {
    const int row = blockIdx.x * blockDim.x + threadIdx.x;
    if (row >= B_ * T_) return;
    const float* x = g_x4 + (size_t)row * OUTD_;
    float* o = out + (size_t)row * OUTD_;
#pragma unroll 4
    for (int j = 0; j < 64; j++) o[j] = sigm(x[j]);
    {
        float e[8], mx = -1e30f;
#pragma unroll
        for (int j = 0; j < 8; j++) { e[j] = x[64 + j]; mx = fmaxf(mx, e[j]); }
        float s = 0.f;
#pragma unroll
        for (int j = 0; j < 8; j++) { e[j] = __expf(e[j] - mx); s += e[j]; }
        float inv = 1.f / s;
#pragma unroll
        for (int j = 0; j < 8; j++) o[64 + j] = e[j] * inv;
    }
    {
        float e[16], mx = -1e30f;
#pragma unroll
        for (int j = 0; j < 16; j++) { e[j] = x[72 + j]; mx = fmaxf(mx, e[j]); }
        float s = 0.f;
#pragma unroll
        for (int j = 0; j < 16; j++) { e[j] = __expf(e[j] - mx); s += e[j]; }
        float inv = 1.f / s;
#pragma unroll
        for (int j = 0; j < 16; j++) o[72 + j] = e[j] * inv;
    }
    {
        float e[40], mx = -1e30f;
#pragma unroll
        for (int j = 0; j < 40; j++) { e[j] = x[88 + j]; mx = fmaxf(mx, e[j]); }
        float s = 0.f;
#pragma unroll
        for (int j = 0; j < 40; j++) { e[j] = __expf(e[j] - mx); s += e[j]; }
        float inv = 1.f / s;
#pragma unroll
        for (int j = 0; j < 40; j++) o[88 + j] = e[j] * inv;
    }
}

// ---------------- launch ----------------
extern "C" void kernel_launch(void* const* d_in, const int* in_sizes, int n_in,
                              void* d_out, int out_size) {
    (void)in_sizes; (void)n_in; (void)out_size;
    const float* x0   = (const float*)d_in[0];
    const float* Wi_f = (const float*)d_in[1];
    const float* bi_f = (const float*)d_in[2];
    const float* Wh_f = (const float*)d_in[3];
    const float* bh_f = (const float*)d_in[4];
    const float* Wi_r = (const float*)d_in[5];
    const float* bi_r = (const float*)d_in[6];
    const float* Wh_r = (const float*)d_in[7];
    const float* bh_r = (const float*)d_in[8];
    const float* W1   = (const float*)d_in[9];
    const float* b1   = (const float*)d_in[10];
    const float* W2   = (const float*)d_in[11];
    const float* b2   = (const float*)d_in[12];
    const float* W3   = (const float*)d_in[13];
    const float* b3   = (const float*)d_in[14];
    float* out = (float*)d_out;

    float *p_x1, *p_x2, *p_x3, *p_x4, *p_gx, *p_bpp, *p_wip;
    cudaGetSymbolAddress((void**)&p_x1, g_x1);
    cudaGetSymbolAddress((void**)&p_x2, g_x2);
    cudaGetSymbolAddress((void**)&p_x3, g_x3);
    cudaGetSymbolAddress((void**)&p_x4, g_x4);
    cudaGetSymbolAddress((void**)&p_gx, g_gx);
    cudaGetSymbolAddress((void**)&p_bpp, g_bpp);
    cudaGetSymbolAddress((void**)&p_wip, g_Wip);

    static bool attr_set = false;
    if (!attr_set) {
        cudaFuncSetAttribute(lstm_kernel, cudaFuncAttributeMaxDynamicSharedMemorySize, LSTM_SMEM);
        attr_set = true;
    }

    prep_kernel<<<256, 256>>>(Wh_f, Wh_r, Wi_f, Wi_r, bi_f, bh_f, bi_r, bh_r);

    gemm_kernel<0><<<dim3(G4_ / 128, BT_ / 64), 256>>>(x0, p_wip, p_bpp, p_gx, BT_, G4_, ID_);
    gemm_kernel<0><<<dim3(G4_ / 128, BT_ / 64), 256>>>(x0, p_wip + (size_t)ID_ * G4_, p_bpp + G4_,
                                                       p_gx + (size_t)BT_ * G4_, BT_, G4_, ID_);
    lstm_kernel<<<128, 256, LSTM_SMEM>>>();

    const int M = B_ * T_;
    gemm_kernel<1><<<dim3(HD_ / 128, M / 64), 256>>>(p_x1, W1, b1, p_x2, M, HD_, 2 * HD_);
    gemm_kernel<1><<<dim3(HD_ / 128, M / 64), 256>>>(p_x2, W2, b2, p_x3, M, HD_, HD_);
    gemm_kernel<0><<<dim3(OUTD_ / 128, M / 64), 256>>>(p_x3, W3, b3, p_x4, M, OUTD_, HD_);
    head_kernel<<<(M + 255) / 256, 256>>>(out);
}